// round 6
// baseline (speedup 1.0000x reference)
#include <cuda_runtime.h>
#include <cstdint>

// Problem constants
#define GIBBS_K   10
#define BATCH     65536
#define PAIRS     32768          // BATCH/2 : warp handles (b, b+PAIRS)
#define WPB       8              // warps per block
#define TPB       (WPB*32)
#define NBLOCKS   (PAIRS/WPB)    // 4096

#define HALF_H 8388608u          // (BATCH*ALPHA*N)/2
#define HALF_V 2097152u          // (BATCH*N)/2

struct RbmKeys { uint2 kh[GIBBS_K]; uint2 kv[GIBBS_K]; };

__device__ double g_rbm_sum;

// ---------------------------------------------------------------------------
// JAX threefry2x32 (exact replication)
// ---------------------------------------------------------------------------
__host__ __device__ __forceinline__ unsigned rbm_rotl32(unsigned x, int r) {
    return (x << r) | (x >> (32 - r));
}

__host__ __device__ __forceinline__ void rbm_tf2x32(unsigned k0, unsigned k1,
                                                    unsigned x0, unsigned x1,
                                                    unsigned& o0, unsigned& o1) {
    unsigned ks2 = k0 ^ k1 ^ 0x1BD11BDAu;
    x0 += k0; x1 += k1;
#define TFR(r) { x0 += x1; x1 = rbm_rotl32(x1, r); x1 ^= x0; }
    TFR(13) TFR(15) TFR(26) TFR(6)
    x0 += k1;  x1 += ks2 + 1u;
    TFR(17) TFR(29) TFR(16) TFR(24)
    x0 += ks2; x1 += k0 + 2u;
    TFR(13) TFR(15) TFR(26) TFR(6)
    x0 += k0;  x1 += k1 + 3u;
    TFR(17) TFR(29) TFR(16) TFR(24)
    x0 += k1;  x1 += ks2 + 4u;
    TFR(13) TFR(15) TFR(26) TFR(6)
    x0 += ks2; x1 += k0 + 5u;
#undef TFR
    o0 = x0; o1 = x1;
}

// jax.random.uniform float32: bitcast(bits>>9 | 0x3f800000) - 1
__device__ __forceinline__ float rbm_u01(unsigned b) {
    return __uint_as_float((b >> 9) | 0x3f800000u) - 1.0f;
}

// XLA logistic: sigmoid(x) = 0.5 + 0.5*tanh(0.5*x)
__device__ __forceinline__ float rbm_sigmoid(float x) {
    return 0.5f + 0.5f * tanhf(0.5f * x);
}

// jnp.logaddexp(x, 0)
__device__ __forceinline__ float rbm_softplus(float x) {
    return fmaxf(x, 0.0f) + log1pf(expf(-fabsf(x)));
}

__device__ __forceinline__ float rbm_warp_sum(float v) {
    #pragma unroll
    for (int s = 16; s > 0; s >>= 1) v += __shfl_xor_sync(0xffffffffu, v, s);
    return v;
}

// ---------------------------------------------------------------------------
// wv[a][i] = sum_c Tf[a][nib_c(v)][(4c-i)&63]
// Table packed float4 over a: Tf4[n*64+o] = {T[0][n][o], T[1][n][o], T[2][n][o], T[3][n][o]}
// acc[a*2 + ii]: ii=0 -> i=lane, ii=1 -> i=lane+32.
// Conflict-free: idx bank = off&31 distinct per lane (also per quarter-warp for LDS.128).
// ---------------------------------------------------------------------------
__device__ __forceinline__ void rbm_wv4(unsigned mlo, unsigned mhi, int lane,
                                        const float4* __restrict__ Tf4,
                                        float acc[8]) {
    #pragma unroll
    for (int k = 0; k < 8; k++) acc[k] = 0.0f;
    int off = (-lane) & 63;
    #pragma unroll
    for (int c = 0; c < 16; c++) {
        unsigned n = (c < 8) ? ((mlo >> (4 * c)) & 15u)
                             : ((mhi >> (4 * (c - 8))) & 15u);
        int idx = (int)n * 64 + off;
        float4 pA = Tf4[idx];
        float4 pB = Tf4[idx ^ 32];
        acc[0] += pA.x; acc[2] += pA.y; acc[4] += pA.z; acc[6] += pA.w;
        acc[1] += pB.x; acc[3] += pB.y; acc[5] += pB.z; acc[7] += pB.w;
        off = (off + 4) & 63;
    }
}

// ---------------------------------------------------------------------------
// wh[i] = sum_a sum_m h_a[m] * K[a][(i-1-m)&63]
//       = sum_a sum_c TbH[a][nib_c(h_a)][(4c-i)&63]
// with TbH[a][n][o] = sum_t bit_t(n) * K[a][(63-o-t)&63]   (Kb[a][y]=K[a][63-y])
// Conflict-free: word bank = off&31, distinct per lane.
// ---------------------------------------------------------------------------
__device__ __forceinline__ void rbm_wh4(const unsigned hl[4], const unsigned hh[4],
                                        int lane, const float* __restrict__ TbH,
                                        float& w0, float& w1) {
    float s0 = 0.0f, s1 = 0.0f;
    int off = (-lane) & 63;
    #pragma unroll
    for (int c = 0; c < 16; c++) {
        #pragma unroll
        for (int a = 0; a < 4; a++) {
            unsigned n = (c < 8) ? ((hl[a] >> (4 * c)) & 15u)
                                 : ((hh[a] >> (4 * (c - 8))) & 15u);
            int idx = a * 1024 + (int)n * 64 + off;
            s0 += TbH[idx];
            s1 += TbH[idx ^ 32];
        }
        off = (off + 4) & 63;
    }
    w0 = s0; w1 = s1;
}

__device__ __forceinline__ float rbm_fe(unsigned mlo, unsigned mhi, int lane,
                                        const float4* __restrict__ Tf4,
                                        const float* __restrict__ csh, float bsc) {
    float acc[8];
    rbm_wv4(mlo, mhi, lane, Tf4, acc);
    float s = 0.0f;
    #pragma unroll
    for (int a = 0; a < 4; a++) {
        float ca = csh[a];
        s += rbm_softplus(acc[a * 2 + 0] + ca);
        s += rbm_softplus(acc[a * 2 + 1] + ca);
    }
    s = rbm_warp_sum(s);
    int pc = __popc(mlo) + __popc(mhi);
    return -bsc * (float)pc - s;
}

// ---------------------------------------------------------------------------
// Main kernel: one warp per sample pair (b, b+32768)
// ---------------------------------------------------------------------------
__global__ void __launch_bounds__(TPB)
rbm_gibbs_kernel(const float* __restrict__ v_data,
                 const float* __restrict__ kern,    // [4][64]
                 const float* __restrict__ b_scalar,
                 const float* __restrict__ c_vector,
                 RbmKeys keys) {
    __shared__ float4 Tf4[16 * 64];     // 16 KB: [n][o] -> float4 over a
    __shared__ float  TbH[4 * 16 * 64]; // 16 KB: [a][n][o]
    __shared__ float  csh[4];
    __shared__ double wsum[WPB];

    const int tid  = threadIdx.x;
    const int lane = tid & 31;
    const int wid  = tid >> 5;

    // Build Tf4: Tf4[n*64+o].a = sum_t bit_t(n) * K[a][(o+t)&63]
    for (int idx = tid; idx < 16 * 64; idx += TPB) {
        int o = idx & 63, n = idx >> 6;
        float4 s = make_float4(0.f, 0.f, 0.f, 0.f);
        #pragma unroll
        for (int t = 0; t < 4; t++) {
            if ((n >> t) & 1) {
                int j = (o + t) & 63;
                s.x += kern[j];
                s.y += kern[64 + j];
                s.z += kern[128 + j];
                s.w += kern[192 + j];
            }
        }
        Tf4[idx] = s;
    }
    // Build TbH: TbH[a][n][o] = sum_t bit_t(n) * K[a][(63-o-t)&63]
    for (int idx = tid; idx < 4 * 16 * 64; idx += TPB) {
        int o = idx & 63, n = (idx >> 6) & 15, a = idx >> 10;
        float s = 0.0f;
        #pragma unroll
        for (int t = 0; t < 4; t++)
            if ((n >> t) & 1) s += kern[a * 64 + ((63 - o - t + 64) & 63)];
        TbH[idx] = s;
    }
    if (tid < 4) csh[tid] = c_vector[tid];
    __syncthreads();

    const float bsc = b_scalar[0];
    const int w  = blockIdx.x * WPB + wid;   // pair index
    const int b0 = w;
    const int b1 = w + PAIRS;

    // Load v_data as bitmasks (bit i = v[i] != 0)
    unsigned m0l, m0h, m1l, m1h;
    {
        float a0 = v_data[(size_t)b0 * 64 + lane];
        float a1 = v_data[(size_t)b0 * 64 + lane + 32];
        m0l = __ballot_sync(0xffffffffu, a0 != 0.0f);
        m0h = __ballot_sync(0xffffffffu, a1 != 0.0f);
        float c0 = v_data[(size_t)b1 * 64 + lane];
        float c1 = v_data[(size_t)b1 * 64 + lane + 32];
        m1l = __ballot_sync(0xffffffffu, c0 != 0.0f);
        m1h = __ballot_sync(0xffffffffu, c1 != 0.0f);
    }

    const float fed0 = rbm_fe(m0l, m0h, lane, Tf4, csh, bsc);
    const float fed1 = rbm_fe(m1l, m1h, lane, Tf4, csh, bsc);

    const unsigned baseH = (unsigned)b0 * 256u;
    const unsigned baseV = (unsigned)b0 * 64u + (unsigned)lane;

    // Gibbs chain
    #pragma unroll 1
    for (int t = 0; t < GIBBS_K; t++) {
        float acc0[8], acc1[8];
        rbm_wv4(m0l, m0h, lane, Tf4, acc0);
        rbm_wv4(m1l, m1h, lane, Tf4, acc1);

        const uint2 kh = keys.kh[t];
        unsigned h0l[4], h0h[4], h1l[4], h1h[4];
        #pragma unroll
        for (int a = 0; a < 4; a++) {
            const float ca = csh[a];
            unsigned cA = baseH + (unsigned)(a * 64 + lane);   // ii=0
            unsigned cB = cA + 32u;                             // ii=1
            unsigned rA0, rA1, rB0, rB1;
            rbm_tf2x32(kh.x, kh.y, cA, cA + HALF_H, rA0, rA1);
            rbm_tf2x32(kh.x, kh.y, cB, cB + HALF_H, rB0, rB1);
            bool s0i0 = rbm_u01(rA0) < rbm_sigmoid(acc0[a * 2 + 0] + ca);
            bool s1i0 = rbm_u01(rA1) < rbm_sigmoid(acc1[a * 2 + 0] + ca);
            bool s0i1 = rbm_u01(rB0) < rbm_sigmoid(acc0[a * 2 + 1] + ca);
            bool s1i1 = rbm_u01(rB1) < rbm_sigmoid(acc1[a * 2 + 1] + ca);
            h0l[a] = __ballot_sync(0xffffffffu, s0i0);
            h0h[a] = __ballot_sync(0xffffffffu, s0i1);
            h1l[a] = __ballot_sync(0xffffffffu, s1i0);
            h1h[a] = __ballot_sync(0xffffffffu, s1i1);
        }

        float wh00, wh01, wh10, wh11;
        rbm_wh4(h0l, h0h, lane, TbH, wh00, wh01);
        rbm_wh4(h1l, h1h, lane, TbH, wh10, wh11);

        const uint2 kv = keys.kv[t];
        unsigned r00, r01, r10, r11;
        rbm_tf2x32(kv.x, kv.y, baseV,       baseV + HALF_V,       r00, r01);
        rbm_tf2x32(kv.x, kv.y, baseV + 32u, baseV + 32u + HALF_V, r10, r11);
        bool s0i0 = rbm_u01(r00) < rbm_sigmoid(wh00 + bsc);
        bool s1i0 = rbm_u01(r01) < rbm_sigmoid(wh10 + bsc);
        bool s0i1 = rbm_u01(r10) < rbm_sigmoid(wh01 + bsc);
        bool s1i1 = rbm_u01(r11) < rbm_sigmoid(wh11 + bsc);
        m0l = __ballot_sync(0xffffffffu, s0i0);
        m0h = __ballot_sync(0xffffffffu, s0i1);
        m1l = __ballot_sync(0xffffffffu, s1i0);
        m1h = __ballot_sync(0xffffffffu, s1i1);
    }

    const float fem0 = rbm_fe(m0l, m0h, lane, Tf4, csh, bsc);
    const float fem1 = rbm_fe(m1l, m1h, lane, Tf4, csh, bsc);
    const float diff = (fed0 - fem0) + (fed1 - fem1);

    if (lane == 0) wsum[wid] = (double)diff;
    __syncthreads();
    if (tid == 0) {
        double s = 0.0;
        #pragma unroll
        for (int i = 0; i < WPB; i++) s += wsum[i];
        atomicAdd(&g_rbm_sum, s);
    }
}

__global__ void rbm_zero_kernel() { g_rbm_sum = 0.0; }

__global__ void rbm_final_kernel(float* __restrict__ out) {
    out[0] = (float)(g_rbm_sum / (double)BATCH);
}

// ---------------------------------------------------------------------------
// Host: replicate scan key-split chain: key(42) -> per step split(k,3)
// ---------------------------------------------------------------------------
extern "C" void kernel_launch(void* const* d_in, const int* in_sizes, int n_in,
                              void* d_out, int out_size) {
    const float* v_data   = (const float*)d_in[0];
    const float* kern     = (const float*)d_in[1];
    const float* b_scalar = (const float*)d_in[2];
    const float* c_vector = (const float*)d_in[3];

    RbmKeys keys;
    unsigned k0 = 0u, k1 = 42u;
    for (int t = 0; t < GIBBS_K; t++) {
        unsigned A0, B0, A1, B1, A2, B2;
        rbm_tf2x32(k0, k1, 0u, 3u, A0, B0);
        rbm_tf2x32(k0, k1, 1u, 4u, A1, B1);
        rbm_tf2x32(k0, k1, 2u, 5u, A2, B2);
        keys.kh[t] = make_uint2(A2, B0);  // keys[1]
        keys.kv[t] = make_uint2(B1, B2);  // keys[2]
        k0 = A0; k1 = A1;                 // carried key
    }

    rbm_zero_kernel<<<1, 1>>>();
    rbm_gibbs_kernel<<<NBLOCKS, TPB>>>(v_data, kern, b_scalar, c_vector, keys);
    rbm_final_kernel<<<1, 1>>>((float*)d_out);
}

// round 7
// speedup vs baseline: 1.5874x; 1.5874x over previous
#include <cuda_runtime.h>
#include <cstdint>

#define GIBBS_K   10
#define BATCH     65536
#define PAIRS     32768          // BATCH/2 : warp handles (b, b+PAIRS)
#define WPB       8
#define TPB       (WPB*32)
#define NBLOCKS   (PAIRS/WPB)    // 4096

#define HALF_H 8388608u          // (BATCH*ALPHA*N)/2
#define HALF_V 2097152u          // (BATCH*N)/2

typedef unsigned long long u64;

struct RbmKeys { uint2 kh[GIBBS_K]; uint2 kv[GIBBS_K]; };

__device__ double   g_rbm_sum = 0.0;
__device__ unsigned g_rbm_cnt = 0u;

// ---------------------------------------------------------------------------
// JAX threefry2x32 (exact)
// ---------------------------------------------------------------------------
__host__ __device__ __forceinline__ unsigned rbm_rotl32(unsigned x, int r) {
#ifdef __CUDA_ARCH__
    return __funnelshift_l(x, x, r);
#else
    return (x << r) | (x >> (32 - r));
#endif
}

__host__ __device__ __forceinline__ void rbm_tf2x32(unsigned k0, unsigned k1,
                                                    unsigned x0, unsigned x1,
                                                    unsigned& o0, unsigned& o1) {
    unsigned ks2 = k0 ^ k1 ^ 0x1BD11BDAu;
    x0 += k0; x1 += k1;
#define TFR(r) { x0 += x1; x1 = rbm_rotl32(x1, r); x1 ^= x0; }
    TFR(13) TFR(15) TFR(26) TFR(6)
    x0 += k1;  x1 += ks2 + 1u;
    TFR(17) TFR(29) TFR(16) TFR(24)
    x0 += ks2; x1 += k0 + 2u;
    TFR(13) TFR(15) TFR(26) TFR(6)
    x0 += k0;  x1 += k1 + 3u;
    TFR(17) TFR(29) TFR(16) TFR(24)
    x0 += k1;  x1 += ks2 + 4u;
    TFR(13) TFR(15) TFR(26) TFR(6)
    x0 += ks2; x1 += k0 + 5u;
#undef TFR
    o0 = x0; o1 = x1;
}

// jax.random.uniform f32: bitcast(bits>>9 | 0x3f800000) - 1
__device__ __forceinline__ float rbm_u01(unsigned b) {
    return __uint_as_float((b >> 9) | 0x3f800000u) - 1.0f;
}

// jnp.logaddexp(x,0)
__device__ __forceinline__ float rbm_softplus(float x) {
    return fmaxf(x, 0.0f) + log1pf(expf(-fabsf(x)));
}

__device__ __forceinline__ float rbm_warp_sum(float v) {
    #pragma unroll
    for (int s = 16; s > 0; s >>= 1) v += __shfl_xor_sync(0xffffffffu, v, s);
    return v;
}

// ---------------------------------------------------------------------------
// f32x2 packed helpers (sm_103a)
// ---------------------------------------------------------------------------
__device__ __forceinline__ u64 rbm_pack2(float lo, float hi) {
    u64 r; asm("mov.b64 %0, {%1, %2};" : "=l"(r) : "f"(lo), "f"(hi)); return r;
}
__device__ __forceinline__ void rbm_unpack2(u64 p, float& lo, float& hi) {
    asm("mov.b64 {%0, %1}, %2;" : "=f"(lo), "=f"(hi) : "l"(p));
}
__device__ __forceinline__ u64 rbm_addx2(u64 a, u64 b) {
    u64 r; asm("add.rn.f32x2 %0, %1, %2;" : "=l"(r) : "l"(a), "l"(b)); return r;
}
__device__ __forceinline__ u64 rbm_mulx2(u64 a, u64 b) {
    u64 r; asm("mul.rn.f32x2 %0, %1, %2;" : "=l"(r) : "l"(a), "l"(b)); return r;
}
__device__ __forceinline__ u64 rbm_fmax2(u64 a, u64 b, u64 c) {
    u64 r; asm("fma.rn.f32x2 %0, %1, %2, %3;" : "=l"(r) : "l"(a), "l"(b), "l"(c)); return r;
}
#define RBM_C2(v) rbm_pack2((v), (v))

// Pairwise sigmoid via Eigen/XLA rational tanh: sigmoid(x)=0.5+0.5*tanh(x/2).
// Valid |x/2| <= 7.9; our args are bounded well inside. Error ~1e-7.
__device__ __forceinline__ void rbm_sig_x2(u64 xp, float& pa, float& pb) {
    u64 t  = rbm_mulx2(xp, RBM_C2(0.5f));
    u64 t2 = rbm_mulx2(t, t);
    u64 n  = rbm_fmax2(RBM_C2(-2.76076847742355e-16f), t2, RBM_C2(2.00018790482477e-13f));
    n = rbm_fmax2(n, t2, RBM_C2(-8.60467152213735e-11f));
    n = rbm_fmax2(n, t2, RBM_C2(5.12229709037114e-08f));
    n = rbm_fmax2(n, t2, RBM_C2(1.48572235717979e-05f));
    n = rbm_fmax2(n, t2, RBM_C2(6.37261928875436e-04f));
    n = rbm_fmax2(n, t2, RBM_C2(4.89352455891786e-03f));
    n = rbm_mulx2(n, t);
    u64 d  = rbm_fmax2(RBM_C2(1.19825839466702e-06f), t2, RBM_C2(1.18534705686654e-04f));
    d = rbm_fmax2(d, t2, RBM_C2(2.26843463243900e-03f));
    d = rbm_fmax2(d, t2, RBM_C2(4.89352518554385e-03f));
    float n0, n1, d0, d1;
    rbm_unpack2(n, n0, n1);
    rbm_unpack2(d, d0, d1);
    pa = fmaf(__fdividef(n0, d0), 0.5f, 0.5f);
    pb = fmaf(__fdividef(n1, d1), 0.5f, 0.5f);
}

// ---------------------------------------------------------------------------
// wv: packed accumulation. Tf[n*64+o] = float4 {a0,a1,a2,a3} loaded as ulonglong2.
// P[0]=(a0,a1)@i0  P[1]=(a2,a3)@i0  P[2]=(a0,a1)@i1  P[3]=(a2,a3)@i1
// (i0=lane, i1=lane+32). Sum order identical to scalar version.
// ---------------------------------------------------------------------------
__device__ __forceinline__ void rbm_wv4(unsigned mlo, unsigned mhi, int lane,
                                        const ulonglong2* __restrict__ Tf,
                                        u64 P[4]) {
    P[0] = 0ull; P[1] = 0ull; P[2] = 0ull; P[3] = 0ull;
    int off = (-lane) & 63;
    #pragma unroll
    for (int c = 0; c < 16; c++) {
        unsigned n = (c < 8) ? ((mlo >> (4 * c)) & 15u)
                             : ((mhi >> (4 * (c - 8))) & 15u);
        int idx = (int)n * 64 + off;
        ulonglong2 A = Tf[idx];
        ulonglong2 B = Tf[idx ^ 32];
        P[0] = rbm_addx2(P[0], A.x);
        P[1] = rbm_addx2(P[1], A.y);
        P[2] = rbm_addx2(P[2], B.x);
        P[3] = rbm_addx2(P[3], B.y);
        off = (off + 4) & 63;
    }
}

// ---------------------------------------------------------------------------
// wh: lane l computes outputs (2l, (2l-1)&63) as one packed f32x2 accumulator.
// Tp[(a*16+n)*32+p] = float2( T[a][n][2p], T[a][n][2p+1] ),
// T[a][n][o] = sum_t bit_t(n)*K[a][(63-o-t)&63].  Term order per output == R5.
// ---------------------------------------------------------------------------
__device__ __forceinline__ void rbm_whp(const unsigned hl[4], const unsigned hh[4],
                                        int lane, const u64* __restrict__ Tp,
                                        float& wlo, float& whi) {
    u64 Q = 0ull;
    int p = (-lane) & 31;
    #pragma unroll
    for (int c = 0; c < 16; c++) {
        #pragma unroll
        for (int a = 0; a < 4; a++) {
            unsigned n = (c < 8) ? ((hl[a] >> (4 * c)) & 15u)
                                 : ((hh[a] >> (4 * (c - 8))) & 15u);
            Q = rbm_addx2(Q, Tp[(a * 16 + (int)n) * 32 + p]);
        }
        p = (p + 2) & 31;
    }
    rbm_unpack2(Q, wlo, whi);   // wlo = wh[2l], whi = wh[(2l-1)&63]
}

__device__ __forceinline__ float rbm_fe(unsigned mlo, unsigned mhi, int lane,
                                        const ulonglong2* __restrict__ Tf,
                                        const float* __restrict__ csh, float bsc) {
    u64 P[4];
    rbm_wv4(mlo, mhi, lane, Tf, P);
    float ai0[4], ai1[4];
    rbm_unpack2(P[0], ai0[0], ai0[1]);
    rbm_unpack2(P[1], ai0[2], ai0[3]);
    rbm_unpack2(P[2], ai1[0], ai1[1]);
    rbm_unpack2(P[3], ai1[2], ai1[3]);
    float s = 0.0f;
    #pragma unroll
    for (int a = 0; a < 4; a++) {
        float ca = csh[a];
        s += rbm_softplus(ai0[a] + ca);
        s += rbm_softplus(ai1[a] + ca);
    }
    s = rbm_warp_sum(s);
    int pc = __popc(mlo) + __popc(mhi);
    return -bsc * (float)pc - s;
}

// ---------------------------------------------------------------------------
// Main kernel: one warp per sample pair (b, b+32768)
// ---------------------------------------------------------------------------
__global__ void __launch_bounds__(TPB, 2)
rbm_gibbs_kernel(float* __restrict__ out,
                 const float* __restrict__ v_data,
                 const float* __restrict__ kern,    // [4][64]
                 const float* __restrict__ b_scalar,
                 const float* __restrict__ c_vector,
                 RbmKeys keys) {
    __shared__ ulonglong2 Tf[16 * 64];   // 16 KB
    __shared__ u64 Tp[4 * 16 * 32];      // 16 KB
    __shared__ float csh[4];
    __shared__ double wsum[WPB];

    const int tid  = threadIdx.x;
    const int lane = tid & 31;
    const int wid  = tid >> 5;

    // Build Tf: float view; Tf[n*64+o] = {sum_t bit_t(n)*K[a][(o+t)&63]}_a
    {
        float* Tff = (float*)Tf;
        for (int idx = tid; idx < 16 * 64; idx += TPB) {
            int o = idx & 63, n = idx >> 6;
            float s0 = 0.f, s1 = 0.f, s2 = 0.f, s3 = 0.f;
            #pragma unroll
            for (int t = 0; t < 4; t++) {
                if ((n >> t) & 1) {
                    int j = (o + t) & 63;
                    s0 += kern[j];
                    s1 += kern[64 + j];
                    s2 += kern[128 + j];
                    s3 += kern[192 + j];
                }
            }
            Tff[idx * 4 + 0] = s0; Tff[idx * 4 + 1] = s1;
            Tff[idx * 4 + 2] = s2; Tff[idx * 4 + 3] = s3;
        }
    }
    // Build Tp pairs
    {
        float* Tpf = (float*)Tp;
        for (int idx = tid; idx < 4 * 16 * 32; idx += TPB) {
            int p = idx & 31, n = (idx >> 5) & 15, a = idx >> 9;
            int o0 = 2 * p, o1 = 2 * p + 1;
            float lo = 0.f, hi = 0.f;
            #pragma unroll
            for (int t = 0; t < 4; t++) {
                if ((n >> t) & 1) {
                    lo += kern[a * 64 + ((63 - o0 - t + 64) & 63)];
                    hi += kern[a * 64 + ((63 - o1 - t + 64) & 63)];
                }
            }
            Tpf[idx * 2 + 0] = lo;
            Tpf[idx * 2 + 1] = hi;
        }
    }
    if (tid < 4) csh[tid] = c_vector[tid];
    __syncthreads();

    const float bsc = b_scalar[0];
    const u64 bb2 = rbm_pack2(bsc, bsc);
    const u64 c01 = rbm_pack2(csh[0], csh[1]);
    const u64 c23 = rbm_pack2(csh[2], csh[3]);

    const int w  = blockIdx.x * WPB + wid;
    const int b0 = w;
    const int b1 = w + PAIRS;

    // Load v_data as bitmasks
    unsigned m0l, m0h, m1l, m1h;
    {
        float a0 = v_data[(size_t)b0 * 64 + lane];
        float a1 = v_data[(size_t)b0 * 64 + lane + 32];
        m0l = __ballot_sync(0xffffffffu, a0 != 0.0f);
        m0h = __ballot_sync(0xffffffffu, a1 != 0.0f);
        float c0 = v_data[(size_t)b1 * 64 + lane];
        float c1 = v_data[(size_t)b1 * 64 + lane + 32];
        m1l = __ballot_sync(0xffffffffu, c0 != 0.0f);
        m1h = __ballot_sync(0xffffffffu, c1 != 0.0f);
    }

    const float fed0 = rbm_fe(m0l, m0h, lane, Tf, csh, bsc);
    const float fed1 = rbm_fe(m1l, m1h, lane, Tf, csh, bsc);

    const unsigned baseH = (unsigned)b0 * 256u;
    const unsigned baseV = (unsigned)b0 * 64u + (unsigned)lane;

    #pragma unroll 1
    for (int t = 0; t < GIBBS_K; t++) {
        u64 P0[4], P1[4];
        rbm_wv4(m0l, m0h, lane, Tf, P0);
        rbm_wv4(m1l, m1h, lane, Tf, P1);

        // p_h values: ph[a*2+ii]
        float ph0[8], ph1[8];
        {
            float x, y;
            rbm_sig_x2(rbm_addx2(P0[0], c01), x, y); ph0[0] = x; ph0[2] = y;
            rbm_sig_x2(rbm_addx2(P0[1], c23), x, y); ph0[4] = x; ph0[6] = y;
            rbm_sig_x2(rbm_addx2(P0[2], c01), x, y); ph0[1] = x; ph0[3] = y;
            rbm_sig_x2(rbm_addx2(P0[3], c23), x, y); ph0[5] = x; ph0[7] = y;
            rbm_sig_x2(rbm_addx2(P1[0], c01), x, y); ph1[0] = x; ph1[2] = y;
            rbm_sig_x2(rbm_addx2(P1[1], c23), x, y); ph1[4] = x; ph1[6] = y;
            rbm_sig_x2(rbm_addx2(P1[2], c01), x, y); ph1[1] = x; ph1[3] = y;
            rbm_sig_x2(rbm_addx2(P1[3], c23), x, y); ph1[5] = x; ph1[7] = y;
        }

        const uint2 kh = keys.kh[t];
        unsigned h0l[4], h0h[4], h1l[4], h1h[4];
        #pragma unroll
        for (int a = 0; a < 4; a++) {
            unsigned cA = baseH + (unsigned)(a * 64 + lane);
            unsigned cB = cA + 32u;
            unsigned rA0, rA1, rB0, rB1;
            rbm_tf2x32(kh.x, kh.y, cA, cA + HALF_H, rA0, rA1);
            rbm_tf2x32(kh.x, kh.y, cB, cB + HALF_H, rB0, rB1);
            h0l[a] = __ballot_sync(0xffffffffu, rbm_u01(rA0) < ph0[a * 2 + 0]);
            h0h[a] = __ballot_sync(0xffffffffu, rbm_u01(rB0) < ph0[a * 2 + 1]);
            h1l[a] = __ballot_sync(0xffffffffu, rbm_u01(rA1) < ph1[a * 2 + 0]);
            h1h[a] = __ballot_sync(0xffffffffu, rbm_u01(rB1) < ph1[a * 2 + 1]);
        }

        // wh packed at outputs (2l, 2l-1), then remap to (lane, lane+32)
        float w0lo, w0hi, w1lo, w1hi;
        rbm_whp(h0l, h0h, lane, Tp, w0lo, w0hi);
        rbm_whp(h1l, h1h, lane, Tp, w1lo, w1hi);

        const int src  = (lane + 1) >> 1;
        const int src2 = src + 16;          // shfl wraps mod 32
        float s0 = __shfl_sync(0xffffffffu, w0lo, src);
        float t0 = __shfl_sync(0xffffffffu, w0hi, src);
        float s1 = __shfl_sync(0xffffffffu, w0lo, src2);
        float t1 = __shfl_sync(0xffffffffu, w0hi, src2);
        float u0 = __shfl_sync(0xffffffffu, w1lo, src);
        float v0 = __shfl_sync(0xffffffffu, w1hi, src);
        float u1 = __shfl_sync(0xffffffffu, w1lo, src2);
        float v1 = __shfl_sync(0xffffffffu, w1hi, src2);
        const bool odd = (lane & 1);
        float wh00 = odd ? t0 : s0;   // sample0, i=lane
        float wh01 = odd ? t1 : s1;   // sample0, i=lane+32
        float wh10 = odd ? v0 : u0;   // sample1, i=lane
        float wh11 = odd ? v1 : u1;   // sample1, i=lane+32

        float pv00, pv01, pv10, pv11;
        {
            float x, y;
            rbm_sig_x2(rbm_addx2(rbm_pack2(wh00, wh01), bb2), x, y); pv00 = x; pv01 = y;
            rbm_sig_x2(rbm_addx2(rbm_pack2(wh10, wh11), bb2), x, y); pv10 = x; pv11 = y;
        }

        const uint2 kv = keys.kv[t];
        unsigned r00, r01, r10, r11;
        rbm_tf2x32(kv.x, kv.y, baseV,       baseV + HALF_V,       r00, r01);
        rbm_tf2x32(kv.x, kv.y, baseV + 32u, baseV + 32u + HALF_V, r10, r11);
        m0l = __ballot_sync(0xffffffffu, rbm_u01(r00) < pv00);
        m0h = __ballot_sync(0xffffffffu, rbm_u01(r10) < pv01);
        m1l = __ballot_sync(0xffffffffu, rbm_u01(r01) < pv10);
        m1h = __ballot_sync(0xffffffffu, rbm_u01(r11) < pv11);
    }

    const float fem0 = rbm_fe(m0l, m0h, lane, Tf, csh, bsc);
    const float fem1 = rbm_fe(m1l, m1h, lane, Tf, csh, bsc);
    const float diff = (fed0 - fem0) + (fed1 - fem1);

    if (lane == 0) wsum[wid] = (double)diff;
    __syncthreads();
    if (tid == 0) {
        double s = 0.0;
        #pragma unroll
        for (int i = 0; i < WPB; i++) s += wsum[i];
        atomicAdd(&g_rbm_sum, s);
        __threadfence();
        unsigned ticket = atomicAdd(&g_rbm_cnt, 1u);
        if (ticket == NBLOCKS - 1) {
            __threadfence();
            double total = atomicAdd(&g_rbm_sum, 0.0);   // fenced read
            out[0] = (float)(total / (double)BATCH);
            g_rbm_sum = 0.0;        // reset for next graph replay
            g_rbm_cnt = 0u;
        }
    }
}

// ---------------------------------------------------------------------------
// Host: replicate scan key-split chain: key(42); per step k,kh,kv = split(k,3)
// ---------------------------------------------------------------------------
extern "C" void kernel_launch(void* const* d_in, const int* in_sizes, int n_in,
                              void* d_out, int out_size) {
    const float* v_data   = (const float*)d_in[0];
    const float* kern     = (const float*)d_in[1];
    const float* b_scalar = (const float*)d_in[2];
    const float* c_vector = (const float*)d_in[3];

    RbmKeys keys;
    unsigned k0 = 0u, k1 = 42u;
    for (int t = 0; t < GIBBS_K; t++) {
        unsigned A0, B0, A1, B1, A2, B2;
        rbm_tf2x32(k0, k1, 0u, 3u, A0, B0);
        rbm_tf2x32(k0, k1, 1u, 4u, A1, B1);
        rbm_tf2x32(k0, k1, 2u, 5u, A2, B2);
        keys.kh[t] = make_uint2(A2, B0);  // keys[1]
        keys.kv[t] = make_uint2(B1, B2);  // keys[2]
        k0 = A0; k1 = A1;                 // carried key
    }

    rbm_gibbs_kernel<<<NBLOCKS, TPB>>>((float*)d_out, v_data, kern,
                                       b_scalar, c_vector, keys);
}

// round 8
// speedup vs baseline: 2.0215x; 1.2735x over previous
#include <cuda_runtime.h>
#include <cstdint>

#define GIBBS_K   10
#define BATCH     65536
#define PAIRS     32768          // BATCH/2 : warp handles (b, b+PAIRS)
#define WPB       8
#define TPB       (WPB*32)
#define NBLOCKS   (PAIRS/WPB)    // 4096

#define HALF_H 8388608u          // (BATCH*ALPHA*N)/2
#define HALF_V 2097152u          // (BATCH*N)/2

#define SMEM_TF_BYTES 32768      // wv radix-32 table: 32n x 64o x float4
#define SMEM_TQ_BYTES 65536      // wh radix-64 pair table: 4a x 64n x 32p x float2
#define SMEM_BYTES    (SMEM_TF_BYTES + SMEM_TQ_BYTES)

typedef unsigned long long u64;

struct RbmKeys { uint2 kh[GIBBS_K]; uint2 kv[GIBBS_K]; };

__device__ double   g_rbm_sum = 0.0;
__device__ unsigned g_rbm_cnt = 0u;
__device__ float4   gTf[32 * 64];   // [n][o] -> {a0,a1,a2,a3}
__device__ float4   gTq[4096];      // pairs of float2 entries

// ---------------------------------------------------------------------------
// JAX threefry2x32 (exact)
// ---------------------------------------------------------------------------
__host__ __device__ __forceinline__ unsigned rbm_rotl32(unsigned x, int r) {
#ifdef __CUDA_ARCH__
    return __funnelshift_l(x, x, r);
#else
    return (x << r) | (x >> (32 - r));
#endif
}

__host__ __device__ __forceinline__ void rbm_tf2x32(unsigned k0, unsigned k1,
                                                    unsigned x0, unsigned x1,
                                                    unsigned& o0, unsigned& o1) {
    unsigned ks2 = k0 ^ k1 ^ 0x1BD11BDAu;
    x0 += k0; x1 += k1;
#define TFR(r) { x0 += x1; x1 = rbm_rotl32(x1, r); x1 ^= x0; }
    TFR(13) TFR(15) TFR(26) TFR(6)
    x0 += k1;  x1 += ks2 + 1u;
    TFR(17) TFR(29) TFR(16) TFR(24)
    x0 += ks2; x1 += k0 + 2u;
    TFR(13) TFR(15) TFR(26) TFR(6)
    x0 += k0;  x1 += k1 + 3u;
    TFR(17) TFR(29) TFR(16) TFR(24)
    x0 += k1;  x1 += ks2 + 4u;
    TFR(13) TFR(15) TFR(26) TFR(6)
    x0 += ks2; x1 += k0 + 5u;
#undef TFR
    o0 = x0; o1 = x1;
}

// jax.random.uniform f32: bitcast(bits>>9 | 0x3f800000) - 1
__device__ __forceinline__ float rbm_u01(unsigned b) {
    return __uint_as_float((b >> 9) | 0x3f800000u) - 1.0f;
}

// jnp.logaddexp(x,0)
__device__ __forceinline__ float rbm_softplus(float x) {
    return fmaxf(x, 0.0f) + log1pf(expf(-fabsf(x)));
}

__device__ __forceinline__ float rbm_warp_sum(float v) {
    #pragma unroll
    for (int s = 16; s > 0; s >>= 1) v += __shfl_xor_sync(0xffffffffu, v, s);
    return v;
}

// ---------------------------------------------------------------------------
// f32x2 packed helpers
// ---------------------------------------------------------------------------
__device__ __forceinline__ u64 rbm_pack2(float lo, float hi) {
    u64 r; asm("mov.b64 %0, {%1, %2};" : "=l"(r) : "f"(lo), "f"(hi)); return r;
}
__device__ __forceinline__ void rbm_unpack2(u64 p, float& lo, float& hi) {
    asm("mov.b64 {%0, %1}, %2;" : "=f"(lo), "=f"(hi) : "l"(p));
}
__device__ __forceinline__ u64 rbm_addx2(u64 a, u64 b) {
    u64 r; asm("add.rn.f32x2 %0, %1, %2;" : "=l"(r) : "l"(a), "l"(b)); return r;
}

// Bernoulli draw: u < 1/(1+e)  <=>  fma(u, e, u) < 1,  e = exp(-x)
__device__ __forceinline__ bool rbm_draw(unsigned bits, float e) {
    float u = rbm_u01(bits);
    return fmaf(u, e, u) < 1.0f;
}

// ---------------------------------------------------------------------------
// Pre-kernel: build LUTs once (1 block).
// gTf[n*64+o].a  = sum_{t<5} bit_t(n) * K[a][(o+t)&63]
// gTq entry (a,n,p) float2:
//   e0 = sum_{t<6} bit_t(n) * K[a][(2p-1-t)&63]   (output i=2p)
//   e1 = sum_{t<6} bit_t(n) * K[a][(2p-2-t)&63]   (output i=2p-1)
// packed two entries (p0, p0+1) per float4.
// ---------------------------------------------------------------------------
__global__ void rbm_build_tables(const float* __restrict__ kern) {
    const int tid = threadIdx.x;
    for (int idx = tid; idx < 32 * 64; idx += 256) {
        int o = idx & 63, n = idx >> 6;
        float4 s = make_float4(0.f, 0.f, 0.f, 0.f);
        #pragma unroll
        for (int t = 0; t < 5; t++) {
            if ((n >> t) & 1) {
                int j = (o + t) & 63;
                s.x += kern[j];
                s.y += kern[64 + j];
                s.z += kern[128 + j];
                s.w += kern[192 + j];
            }
        }
        gTf[idx] = s;
    }
    for (int idx2 = tid; idx2 < 4096; idx2 += 256) {
        int a = idx2 >> 10, n = (idx2 >> 4) & 63, p0 = (idx2 & 15) * 2;
        float4 r = make_float4(0.f, 0.f, 0.f, 0.f);
        #pragma unroll
        for (int t = 0; t < 6; t++) {
            if ((n >> t) & 1) {
                r.x += kern[a * 64 + ((2 * p0 - 1 - t + 128) & 63)];
                r.y += kern[a * 64 + ((2 * p0 - 2 - t + 128) & 63)];
                r.z += kern[a * 64 + ((2 * p0 + 1 - t + 128) & 63)];
                r.w += kern[a * 64 + ((2 * p0 - t + 128) & 63)];
            }
        }
        gTq[idx2] = r;
    }
}

// ---------------------------------------------------------------------------
// wv radix-32: 13 chunks of 5 bits.  off = (5c - i) & 63.
// P[0]=(a0,a1)@i0  P[1]=(a2,a3)@i0  P[2]=(a0,a1)@i1  P[3]=(a2,a3)@i1
// ---------------------------------------------------------------------------
__device__ __forceinline__ void rbm_wv32(u64 v, int lane,
                                         const ulonglong2* __restrict__ Tf,
                                         u64 P[4]) {
    P[0] = 0ull; P[1] = 0ull; P[2] = 0ull; P[3] = 0ull;
    int off = (-lane) & 63;
    #pragma unroll
    for (int c = 0; c < 13; c++) {
        unsigned n = (unsigned)(v >> (5 * c)) & 31u;
        int idx = (int)n * 64 + off;
        ulonglong2 A = Tf[idx];
        ulonglong2 B = Tf[idx ^ 32];
        P[0] = rbm_addx2(P[0], A.x);
        P[1] = rbm_addx2(P[1], A.y);
        P[2] = rbm_addx2(P[2], B.x);
        P[3] = rbm_addx2(P[3], B.y);
        off = (off + 5) & 63;
    }
}

// ---------------------------------------------------------------------------
// wh radix-64: 11 chunks of 6 bits per alpha. Lane l accumulates packed
// outputs (2l, (2l-1)&63); table index p' = (l - 3c) & 31.
// ---------------------------------------------------------------------------
__device__ __forceinline__ void rbm_wh64(const u64 h[4], int lane,
                                         const u64* __restrict__ Tq,
                                         float& wlo, float& whi) {
    u64 Q = 0ull;
    int p = lane;
    #pragma unroll
    for (int c = 0; c < 11; c++) {
        #pragma unroll
        for (int a = 0; a < 4; a++) {
            unsigned n = (unsigned)(h[a] >> (6 * c)) & 63u;
            Q = rbm_addx2(Q, Tq[(a * 64 + (int)n) * 32 + p]);
        }
        p = (p + 29) & 31;   // -3 mod 32
    }
    rbm_unpack2(Q, wlo, whi);   // wlo = wh[2l], whi = wh[(2l-1)&63]
}

__device__ __noinline__ float rbm_fe(u64 v, int lane,
                                     const ulonglong2* __restrict__ Tf,
                                     const float* __restrict__ csh, float bsc) {
    u64 P[4];
    rbm_wv32(v, lane, Tf, P);
    float ai0[4], ai1[4];
    rbm_unpack2(P[0], ai0[0], ai0[1]);
    rbm_unpack2(P[1], ai0[2], ai0[3]);
    rbm_unpack2(P[2], ai1[0], ai1[1]);
    rbm_unpack2(P[3], ai1[2], ai1[3]);
    float s = 0.0f;
    #pragma unroll
    for (int a = 0; a < 4; a++) {
        float ca = csh[a];
        s += rbm_softplus(ai0[a] + ca);
        s += rbm_softplus(ai1[a] + ca);
    }
    s = rbm_warp_sum(s);
    return -bsc * (float)__popcll(v) - s;
}

// ---------------------------------------------------------------------------
// Main kernel: one warp per sample pair (b, b+32768)
// ---------------------------------------------------------------------------
__global__ void __launch_bounds__(TPB, 2)
rbm_gibbs_kernel(float* __restrict__ out,
                 const float* __restrict__ v_data,
                 const float* __restrict__ b_scalar,
                 const float* __restrict__ c_vector,
                 RbmKeys keys) {
    extern __shared__ char smem_dyn[];
    ulonglong2* Tf = (ulonglong2*)smem_dyn;
    u64*        Tq = (u64*)(smem_dyn + SMEM_TF_BYTES);
    __shared__ float  csh[4];
    __shared__ double wsum[WPB];

    const int tid  = threadIdx.x;
    const int lane = tid & 31;
    const int wid  = tid >> 5;

    // Copy LUTs from global (L2-resident) to shared
    {
        float4* sf = (float4*)smem_dyn;
        for (int i = tid; i < 32 * 64; i += TPB) sf[i] = gTf[i];
        float4* sq = (float4*)(smem_dyn + SMEM_TF_BYTES);
        for (int i = tid; i < 4096; i += TPB) sq[i] = gTq[i];
    }
    if (tid < 4) csh[tid] = c_vector[tid];
    __syncthreads();

    const float bsc = b_scalar[0];
    const int w  = blockIdx.x * WPB + wid;
    const int b0 = w;
    const int b1 = w + PAIRS;

    // Load v_data as bitmasks
    u64 v0, v1;
    {
        float a0 = v_data[(size_t)b0 * 64 + lane];
        float a1 = v_data[(size_t)b0 * 64 + lane + 32];
        unsigned lo = __ballot_sync(0xffffffffu, a0 != 0.0f);
        unsigned hi = __ballot_sync(0xffffffffu, a1 != 0.0f);
        v0 = (u64)lo | ((u64)hi << 32);
        float c0 = v_data[(size_t)b1 * 64 + lane];
        float c1 = v_data[(size_t)b1 * 64 + lane + 32];
        lo = __ballot_sync(0xffffffffu, c0 != 0.0f);
        hi = __ballot_sync(0xffffffffu, c1 != 0.0f);
        v1 = (u64)lo | ((u64)hi << 32);
    }

    const float fed0 = rbm_fe(v0, lane, Tf, csh, bsc);
    const float fed1 = rbm_fe(v1, lane, Tf, csh, bsc);

    const unsigned baseH = (unsigned)b0 * 256u;
    const unsigned baseV = (unsigned)b0 * 64u + (unsigned)lane;

    #pragma unroll 1
    for (int t = 0; t < GIBBS_K; t++) {
        u64 P0[4], P1[4];
        rbm_wv32(v0, lane, Tf, P0);
        rbm_wv32(v1, lane, Tf, P1);

        // e = exp(-(wv + c)) per (sample, a, ii); layout e[s][a*2+ii]
        float e0[8], e1[8];
        {
            float x, y;
            rbm_unpack2(P0[0], x, y); e0[0] = __expf(-(x + csh[0])); e0[2] = __expf(-(y + csh[1]));
            rbm_unpack2(P0[1], x, y); e0[4] = __expf(-(x + csh[2])); e0[6] = __expf(-(y + csh[3]));
            rbm_unpack2(P0[2], x, y); e0[1] = __expf(-(x + csh[0])); e0[3] = __expf(-(y + csh[1]));
            rbm_unpack2(P0[3], x, y); e0[5] = __expf(-(x + csh[2])); e0[7] = __expf(-(y + csh[3]));
            rbm_unpack2(P1[0], x, y); e1[0] = __expf(-(x + csh[0])); e1[2] = __expf(-(y + csh[1]));
            rbm_unpack2(P1[1], x, y); e1[4] = __expf(-(x + csh[2])); e1[6] = __expf(-(y + csh[3]));
            rbm_unpack2(P1[2], x, y); e1[1] = __expf(-(x + csh[0])); e1[3] = __expf(-(y + csh[1]));
            rbm_unpack2(P1[3], x, y); e1[5] = __expf(-(x + csh[2])); e1[7] = __expf(-(y + csh[3]));
        }

        const uint2 kh = keys.kh[t];
        u64 h0[4], h1[4];
        #pragma unroll
        for (int a = 0; a < 4; a++) {
            unsigned cA = baseH + (unsigned)(a * 64 + lane);
            unsigned cB = cA + 32u;
            unsigned rA0, rA1, rB0, rB1;
            rbm_tf2x32(kh.x, kh.y, cA, cA + HALF_H, rA0, rA1);
            rbm_tf2x32(kh.x, kh.y, cB, cB + HALF_H, rB0, rB1);
            unsigned l0 = __ballot_sync(0xffffffffu, rbm_draw(rA0, e0[a * 2 + 0]));
            unsigned g0 = __ballot_sync(0xffffffffu, rbm_draw(rB0, e0[a * 2 + 1]));
            unsigned l1 = __ballot_sync(0xffffffffu, rbm_draw(rA1, e1[a * 2 + 0]));
            unsigned g1 = __ballot_sync(0xffffffffu, rbm_draw(rB1, e1[a * 2 + 1]));
            h0[a] = (u64)l0 | ((u64)g0 << 32);
            h1[a] = (u64)l1 | ((u64)g1 << 32);
        }

        // wh packed at outputs (2l, 2l-1), then remap to (lane, lane+32)
        float w0lo, w0hi, w1lo, w1hi;
        rbm_wh64(h0, lane, Tq, w0lo, w0hi);
        rbm_wh64(h1, lane, Tq, w1lo, w1hi);

        const int src  = (lane + 1) >> 1;
        const int src2 = src + 16;          // shfl wraps mod 32
        float s0 = __shfl_sync(0xffffffffu, w0lo, src);
        float t0 = __shfl_sync(0xffffffffu, w0hi, src);
        float s1 = __shfl_sync(0xffffffffu, w0lo, src2);
        float t1 = __shfl_sync(0xffffffffu, w0hi, src2);
        float u0 = __shfl_sync(0xffffffffu, w1lo, src);
        float q0 = __shfl_sync(0xffffffffu, w1hi, src);
        float u1 = __shfl_sync(0xffffffffu, w1lo, src2);
        float q1 = __shfl_sync(0xffffffffu, w1hi, src2);
        const bool odd = (lane & 1);
        float wh00 = odd ? t0 : s0;   // sample0, i=lane
        float wh01 = odd ? t1 : s1;   // sample0, i=lane+32
        float wh10 = odd ? q0 : u0;   // sample1, i=lane
        float wh11 = odd ? q1 : u1;   // sample1, i=lane+32

        float ev00 = __expf(-(wh00 + bsc));
        float ev01 = __expf(-(wh01 + bsc));
        float ev10 = __expf(-(wh10 + bsc));
        float ev11 = __expf(-(wh11 + bsc));

        const uint2 kv = keys.kv[t];
        unsigned r00, r01, r10, r11;
        rbm_tf2x32(kv.x, kv.y, baseV,       baseV + HALF_V,       r00, r01);
        rbm_tf2x32(kv.x, kv.y, baseV + 32u, baseV + 32u + HALF_V, r10, r11);
        unsigned m0l = __ballot_sync(0xffffffffu, rbm_draw(r00, ev00));
        unsigned m0h = __ballot_sync(0xffffffffu, rbm_draw(r10, ev01));
        unsigned m1l = __ballot_sync(0xffffffffu, rbm_draw(r01, ev10));
        unsigned m1h = __ballot_sync(0xffffffffu, rbm_draw(r11, ev11));
        v0 = (u64)m0l | ((u64)m0h << 32);
        v1 = (u64)m1l | ((u64)m1h << 32);
    }

    const float fem0 = rbm_fe(v0, lane, Tf, csh, bsc);
    const float fem1 = rbm_fe(v1, lane, Tf, csh, bsc);
    const float diff = (fed0 - fem0) + (fed1 - fem1);

    if (lane == 0) wsum[wid] = (double)diff;
    __syncthreads();
    if (tid == 0) {
        double s = 0.0;
        #pragma unroll
        for (int i = 0; i < WPB; i++) s += wsum[i];
        atomicAdd(&g_rbm_sum, s);
        __threadfence();
        unsigned ticket = atomicAdd(&g_rbm_cnt, 1u);
        if (ticket == NBLOCKS - 1) {
            __threadfence();
            double total = atomicAdd(&g_rbm_sum, 0.0);
            out[0] = (float)(total / (double)BATCH);
            g_rbm_sum = 0.0;        // reset for next graph replay
            g_rbm_cnt = 0u;
        }
    }
}

// ---------------------------------------------------------------------------
// Host: replicate scan key-split chain: key(42); per step k,kh,kv = split(k,3)
// ---------------------------------------------------------------------------
extern "C" void kernel_launch(void* const* d_in, const int* in_sizes, int n_in,
                              void* d_out, int out_size) {
    const float* v_data   = (const float*)d_in[0];
    const float* kern     = (const float*)d_in[1];
    const float* b_scalar = (const float*)d_in[2];
    const float* c_vector = (const float*)d_in[3];

    RbmKeys keys;
    unsigned k0 = 0u, k1 = 42u;
    for (int t = 0; t < GIBBS_K; t++) {
        unsigned A0, B0, A1, B1, A2, B2;
        rbm_tf2x32(k0, k1, 0u, 3u, A0, B0);
        rbm_tf2x32(k0, k1, 1u, 4u, A1, B1);
        rbm_tf2x32(k0, k1, 2u, 5u, A2, B2);
        keys.kh[t] = make_uint2(A2, B0);  // keys[1]
        keys.kv[t] = make_uint2(B1, B2);  // keys[2]
        k0 = A0; k1 = A1;                 // carried key
    }

    cudaFuncSetAttribute(rbm_gibbs_kernel,
                         cudaFuncAttributeMaxDynamicSharedMemorySize, SMEM_BYTES);

    rbm_build_tables<<<1, 256>>>(kern);
    rbm_gibbs_kernel<<<NBLOCKS, TPB, SMEM_BYTES>>>((float*)d_out, v_data,
                                                   b_scalar, c_vector, keys);
}